// round 16
// baseline (speedup 1.0000x reference)
#include <cuda_runtime.h>
#include <cuda_fp16.h>
#include <cstdint>

#define B_      1024
#define N_      4096
#define L_      8
#define K_      16
#define G_      8            // batch rows per block
#define THREADS_ 1024
#define NBLOCKS_ (B_ / G_)   // 128  (<= 148 SMs -> all blocks co-resident)
#define PREPT_  256          // threads per block doing the schedule slice

// Scratch: schedule-permuted packed pairs: low 16 = index, high 16 = fp16 weight.
__device__ __align__(16) uint32_t g_pair[L_ * N_ * K_];    // 2 MB
// Monotonic arrival counter (never reset; graph replays are sequential, so
// run r's arrivals occupy [128r, 128r+128) and each block spins to (r+1)*128).
__device__ unsigned int g_arrive = 0;

// ---------------------------------------------------------------------------
// Rank-space static-LQF schedule slice (bit-identical picks to R12/R14/R15),
// now a device function run by threads 0..255 of each fused block while the
// other 768 threads load x. Lanes 0-7/8-15/... of a warp are the LDS.128
// crossbar phases; terms commute; per step the 8 lanes should hit distinct
// bank-groups (s & 7). Groups ranked by octet-total count once; first-fit
// __ffs in rank space = "heaviest first".
// ---------------------------------------------------------------------------
__device__ __forceinline__ uint32_t bits_from_bytes(uint64_t eq) {
    return (uint32_t)(((eq & 0x0101010101010101ull) * 0x0102040810204080ull) >> 56);
}

__device__ void prep_slice(const int* __restrict__ src,
                           const float* __restrict__ w,
                           uint32_t* buck, int tid) {
    int gtid  = blockIdx.x * PREPT_ + tid;
    int octet = gtid >> 3;
    int lane8 = gtid & 7;
    int l = octet / (N_ / 8);
    int n = (octet % (N_ / 8)) * 8 + lane8;

    const int*   sp = src + ((size_t)l * N_ + n) * K_;
    const float* wp = w   + ((size_t)l * N_ + n) * K_;

    uint32_t pair[K_];
    uint64_t cnts = 0;
    #pragma unroll
    for (int k = 0; k < K_; k++) {
        uint32_t s16 = (uint32_t)sp[k] & 0xFFFFu;
        uint32_t w16 = (uint32_t)__half_as_ushort(__float2half_rn(wp[k]));
        pair[k] = s16 | (w16 << 16);
        cnts += 1ull << (8 * (s16 & 7));
    }

    uint64_t tot = 0;
    #pragma unroll
    for (int j = 0; j < 8; j++)
        tot += __shfl_sync(0xFFFFFFFFu, (unsigned long long)cnts, j, 8);

    uint32_t permTab = 0, rankOf = 0;
    {
        uint64_t twork = tot;
        uint32_t remg = 0xFFu;
        #pragma unroll
        for (int r = 0; r < 8; r++) {
            uint32_t lo = (uint32_t)twork, hi = (uint32_t)(twork >> 32);
            uint32_t v = __vmaxu4(lo, hi);
            v = __vmaxu4(v, v >> 16);
            v = __vmaxu4(v, v >> 8);
            uint32_t rep = (v & 0xFFu) * 0x01010101u;
            uint64_t eq = ((uint64_t)__vcmpeq4(hi, rep) << 32)
                        | (uint64_t)__vcmpeq4(lo, rep);
            uint32_t matches = bits_from_bytes(eq) & remg;
            int g = __ffs(matches) - 1;
            permTab |= (uint32_t)g << (4 * r);
            rankOf  |= (uint32_t)r << (4 * g);
            remg &= ~(1u << g);
            twork &= ~(0xFFull << (8 * g));
        }
    }

    uint64_t rcnts = 0;
    #pragma unroll
    for (int r = 0; r < 8; r++) {
        int g = (permTab >> (4 * r)) & 7;
        rcnts |= ((cnts >> (8 * g)) & 0xFF) << (8 * r);
    }
    uint64_t rstarts = 0;
    {
        uint32_t acc = 0;
        #pragma unroll
        for (int r = 0; r < 8; r++) {
            rstarts |= (uint64_t)acc << (8 * r);
            acc += (uint32_t)((rcnts >> (8 * r)) & 0xFF);
        }
    }
    uint32_t base = tid * K_;
    {
        uint64_t fill = 0;
        #pragma unroll
        for (int k = 0; k < K_; k++) {
            int r = (rankOf >> (4 * (pair[k] & 7))) & 7;
            uint32_t idx = (uint32_t)((rstarts >> (8 * r)) & 0xFF)
                         + (uint32_t)((fill    >> (8 * r)) & 0xFF);
            fill += 1ull << (8 * r);
            buck[base + idx] = pair[k];
        }
    }

    uint64_t rem[8];
    #pragma unroll
    for (int j = 0; j < 8; j++)
        rem[j] = __shfl_sync(0xFFFFFFFFu, (unsigned long long)rcnts, j, 8);

    uint64_t availAll = 0;
    #pragma unroll
    for (int j = 0; j < 8; j++)
        #pragma unroll
        for (int r = 0; r < 8; r++)
            if ((rem[j] >> (8 * r)) & 0xFF) availAll |= 1ull << (8 * j + r);

    uint64_t mypicks = 0;   // 4 bits per step (rank)
    #pragma unroll
    for (int step = 0; step < K_; step++) {
        uint32_t claimed = 0;
        #pragma unroll
        for (int li = 0; li < 8; li++) {
            const int a = (li + step) & 7;
            uint32_t av = (uint32_t)(availAll >> (8 * a)) & 0xFFu;
            uint32_t m = av & ~claimed;
            if (!m) m = av;                 // forced collision
            int r = __ffs(m) - 1;
            claimed |= 1u << r;
            rem[a] -= 1ull << (8 * r);
            if (!((rem[a] >> (8 * r)) & 0xFF))
                availAll &= ~(1ull << (8 * a + r));
            if (lane8 == a)
                mypicks |= (uint64_t)r << (4 * step);
        }
    }

    uint32_t outv[K_];
    uint64_t remc = rcnts;
    #pragma unroll
    for (int step = 0; step < K_; step++) {
        int r = (int)((mypicks >> (4 * step)) & 15);
        uint32_t c   = (uint32_t)((remc >> (8 * r)) & 0xFF);
        uint32_t idx = (uint32_t)((rstarts >> (8 * r)) & 0xFF) + c - 1;
        remc -= 1ull << (8 * r);
        outv[step] = buck[base + idx];
    }
    uint4* o4 = reinterpret_cast<uint4*>(g_pair + ((size_t)l * N_ + n) * K_);
    o4[0] = make_uint4(outv[0],  outv[1],  outv[2],  outv[3]);
    o4[1] = make_uint4(outv[4],  outv[5],  outv[6],  outv[7]);
    o4[2] = make_uint4(outv[8],  outv[9],  outv[10], outv[11]);
    o4[3] = make_uint4(outv[12], outv[13], outv[14], outv[15]);
}

// ---------------------------------------------------------------------------
// Fused kernel. Phase 1: threads 0-255 compute the schedule slice while
// threads 256-1023 load x into smem. Phase 2: grid-wide release/acquire via
// a monotonic arrival counter (all 128 blocks are co-resident at 1 block/SM,
// so the spin is deadlock-free). Phase 3: the measured-best gather mainloop.
// ---------------------------------------------------------------------------
__device__ __forceinline__ void gather_fma(const __half* __restrict__ cur,
                                           uint32_t p, float* acc) {
    uint32_t s = p & 0xFFFFu;
    float wk = __half2float(__ushort_as_half((unsigned short)(p >> 16)));
    uint4 v = *reinterpret_cast<const uint4*>(cur + s * G_);
    float2 f;
    f = __half22float2(*reinterpret_cast<__half2*>(&v.x));
    acc[0] = fmaf(f.x, wk, acc[0]); acc[1] = fmaf(f.y, wk, acc[1]);
    f = __half22float2(*reinterpret_cast<__half2*>(&v.y));
    acc[2] = fmaf(f.x, wk, acc[2]); acc[3] = fmaf(f.y, wk, acc[3]);
    f = __half22float2(*reinterpret_cast<__half2*>(&v.z));
    acc[4] = fmaf(f.x, wk, acc[4]); acc[5] = fmaf(f.y, wk, acc[5]);
    f = __half22float2(*reinterpret_cast<__half2*>(&v.w));
    acc[6] = fmaf(f.x, wk, acc[6]); acc[7] = fmaf(f.y, wk, acc[7]);
}

__global__ void __launch_bounds__(THREADS_, 1)
genome_fused(const float* __restrict__ x, const int* __restrict__ src,
             const float* __restrict__ w, float* __restrict__ out) {
    extern __shared__ __half sm[];
    __half*   bufA = sm;                                    // [N_][G_] 64 KB
    __half*   bufB = sm + N_ * G_;                          // 64 KB
    uint32_t* buck = reinterpret_cast<uint32_t*>(sm + 2 * N_ * G_);  // 16 KB
    const int tid = threadIdx.x;
    const int b0  = blockIdx.x * G_;

    // Phase 1: schedule slice (threads 0-255) || x load (threads 256-1023).
    if (tid < PREPT_) {
        prep_slice(src, w, buck, tid);
        __threadfence();   // make this thread's g_pair stores device-visible
    } else {
        for (int n = tid - PREPT_; n < N_; n += THREADS_ - PREPT_) {
            __half tmp[G_];
            #pragma unroll
            for (int g = 0; g < G_; g++)
                tmp[g] = __float2half_rn(x[(size_t)(b0 + g) * N_ + n]);
            *reinterpret_cast<uint4*>(bufA + (size_t)n * G_) =
                *reinterpret_cast<uint4*>(tmp);
        }
    }
    __syncthreads();

    // Phase 2: grid-wide release/acquire (deadlock-free: all blocks resident).
    if (tid == 0) {
        unsigned old = atomicAdd(&g_arrive, 1u);
        unsigned target = (old / NBLOCKS_ + 1u) * NBLOCKS_;
        volatile unsigned* p = &g_arrive;
        while (*p < target) { }
        __threadfence();   // acquire: other blocks' g_pair now visible
    }
    __syncthreads();

    // Phase 3: mainloop (measured-best form, unchanged).
    #pragma unroll 1
    for (int l = 0; l < L_; l++) {
        const __half* cur = (l & 1) ? bufB : bufA;
        __half*       nxt = (l & 1) ? bufA : bufB;
        const uint4*  pv  = reinterpret_cast<const uint4*>(g_pair) + (size_t)l * N_ * 4;
        const bool last = (l == L_ - 1);

        #pragma unroll 1
        for (int n = tid; n < N_; n += THREADS_) {
            float acc[G_];
            #pragma unroll
            for (int g = 0; g < G_; g++) acc[g] = 0.0f;

            #pragma unroll
            for (int q = 0; q < 4; q++) {           // 4 pairs per uint4
                uint4 p = pv[n * 4 + q];
                gather_fma(cur, p.x, acc);
                gather_fma(cur, p.y, acc);
                gather_fma(cur, p.z, acc);
                gather_fma(cur, p.w, acc);
            }

            float r[G_];
            #pragma unroll
            for (int g = 0; g < G_; g++)
                asm("tanh.approx.f32 %0, %1;" : "=f"(r[g]) : "f"(acc[g]));

            if (!last) {
                __half2 p[G_ / 2];
                #pragma unroll
                for (int g = 0; g < G_ / 2; g++)
                    p[g] = __floats2half2_rn(r[2 * g], r[2 * g + 1]);
                *reinterpret_cast<uint4*>(nxt + (size_t)n * G_) =
                    *reinterpret_cast<const uint4*>(p);
            } else {
                #pragma unroll
                for (int g = 0; g < G_; g++)
                    out[(size_t)(b0 + g) * N_ + n] = r[g];
            }
        }
        __syncthreads();
    }
}

extern "C" void kernel_launch(void* const* d_in, const int* in_sizes, int n_in,
                              void* d_out, int out_size) {
    const float* x   = (const float*)d_in[0];
    const int*   src = (const int*)d_in[1];
    const float* w   = (const float*)d_in[2];
    float*       out = (float*)d_out;

    size_t smem = (size_t)2 * N_ * G_ * sizeof(__half)     // 128 KB state
                + (size_t)PREPT_ * K_ * sizeof(uint32_t);  // 16 KB bucket
    cudaFuncSetAttribute(genome_fused,
                         cudaFuncAttributeMaxDynamicSharedMemorySize, (int)smem);
    genome_fused<<<NBLOCKS_, THREADS_, smem>>>(x, src, w, out);
}